// round 15
// baseline (speedup 1.0000x reference)
#include <cuda_runtime.h>
#include <cuda_fp16.h>
#include <math.h>
#include <stdint.h>

// Problem constants
#define LL 2048
#define NB 2
#define EE 1024
#define HH 16
#define DD 64
#define FF 4096
#define ROWS (LL*NB)   // 4096

// ---------------- scratch (no allocation allowed) ----------------
__device__ __half g_h  [ROWS*EE];
__device__ __half g_q  [ROWS*EE];
__device__ __half g_k  [ROWS*EE];
__device__ __half g_v  [ROWS*EE];
__device__ __half g_o  [ROWS*EE];
__device__ __half g_h2 [ROWS*EE];
__device__ __half g_mid[(size_t)ROWS*FF];
__device__ float  g_x2 [ROWS*EE];
// fp16 weight copies
__device__ __half g_wq [EE*EE];
__device__ __half g_wk [EE*EE];
__device__ __half g_wv [EE*EE];
__device__ __half g_wo [EE*EE];
__device__ __half g_w1 [FF*EE];
__device__ __half g_w2 [EE*FF];

// ---------------- helpers ----------------
__device__ __forceinline__ uint32_t h2pack(float a, float b) {
    __half2 h = __floats2half2_rn(a, b);
    return *reinterpret_cast<uint32_t*>(&h);
}
__device__ __forceinline__ float fexp2(float x) {
    float y;
    asm("ex2.approx.ftz.f32 %0, %1;" : "=f"(y) : "f"(x));
    return y;
}
__device__ __forceinline__ void mma_f16(float* c, const uint32_t* a, const uint32_t* b) {
    asm volatile(
        "mma.sync.aligned.m16n8k16.row.col.f32.f16.f16.f32 "
        "{%0,%1,%2,%3}, {%4,%5,%6,%7}, {%8,%9}, {%0,%1,%2,%3};\n"
        : "+f"(c[0]), "+f"(c[1]), "+f"(c[2]), "+f"(c[3])
        : "r"(a[0]), "r"(a[1]), "r"(a[2]), "r"(a[3]), "r"(b[0]), "r"(b[1]));
}
__device__ __forceinline__ void ldsm4(uint32_t& r0, uint32_t& r1, uint32_t& r2, uint32_t& r3,
                                      uint32_t addr) {
    asm volatile("ldmatrix.sync.aligned.m8n8.x4.shared.b16 {%0,%1,%2,%3}, [%4];\n"
                 : "=r"(r0), "=r"(r1), "=r"(r2), "=r"(r3) : "r"(addr));
}
__device__ __forceinline__ void ldsm4t(uint32_t& r0, uint32_t& r1, uint32_t& r2, uint32_t& r3,
                                       uint32_t addr) {
    asm volatile("ldmatrix.sync.aligned.m8n8.x4.trans.shared.b16 {%0,%1,%2,%3}, [%4];\n"
                 : "=r"(r0), "=r"(r1), "=r"(r2), "=r"(r3) : "r"(addr));
}
__device__ __forceinline__ void cp16(uint32_t saddr, const void* g) {
    asm volatile("cp.async.cg.shared.global [%0], [%1], 16;\n" :: "r"(saddr), "l"(g));
}
#define CP_COMMIT asm volatile("cp.async.commit_group;\n")
#define CP_WAIT1  asm volatile("cp.async.wait_group 1;\n")

__device__ __forceinline__ float gelu_exact(float t) {
    return 0.5f * t * (1.0f + erff(t * 0.70710678118654752f));
}

// ---------------- f2h for QKV weights only (needed before QKV GEMM) ----------------
__global__ __launch_bounds__(256)
void f2h_qkv(const float4* __restrict__ wq, const float4* __restrict__ wk,
             const float4* __restrict__ wv,
             uint32_t* __restrict__ dq, uint32_t* __restrict__ dk,
             uint32_t* __restrict__ dv)
{
    int i = blockIdx.x * 256 + threadIdx.x;   // 0 .. 786431
    const float4* s; uint32_t* d; int local;
    if (i < 262144)      { s = wq; d = dq; local = i; }
    else if (i < 524288) { s = wk; d = dk; local = i - 262144; }
    else                 { s = wv; d = dv; local = i - 524288; }
    float4 v = s[local];
    *(uint2*)&d[2*local] = make_uint2(h2pack(v.x, v.y), h2pack(v.z, v.w));
}

// ---------------- LayerNorm: fp32 in, fp16 out ----------------
__global__ __launch_bounds__(256)
void ln_kernel(const float* __restrict__ x, const float* __restrict__ w,
               const float* __restrict__ b, __half* __restrict__ out)
{
    int row = blockIdx.x;
    int tid = threadIdx.x;
    const float4* xr = (const float4*)(x + (size_t)row * EE);
    float4 v = xr[tid];
    float s  = v.x + v.y + v.z + v.w;
    float ss = v.x*v.x + v.y*v.y + v.z*v.z + v.w*v.w;
    #pragma unroll
    for (int o = 16; o > 0; o >>= 1) {
        s  += __shfl_xor_sync(0xffffffffu, s,  o);
        ss += __shfl_xor_sync(0xffffffffu, ss, o);
    }
    __shared__ float sbuf[8], ssbuf[8];
    if ((tid & 31) == 0) { sbuf[tid >> 5] = s; ssbuf[tid >> 5] = ss; }
    __syncthreads();
    float ts = 0.f, tss = 0.f;
    #pragma unroll
    for (int i = 0; i < 8; i++) { ts += sbuf[i]; tss += ssbuf[i]; }
    float mean = ts * (1.0f / EE);
    float var  = tss * (1.0f / EE) - mean * mean;
    float inv  = rsqrtf(var + 1e-5f);
    float4 w4 = ((const float4*)w)[tid];
    float4 b4 = ((const float4*)b)[tid];
    uint32_t* orow = (uint32_t*)(out + (size_t)row * EE);
    orow[2*tid]   = h2pack((v.x - mean)*inv*w4.x + b4.x, (v.y - mean)*inv*w4.y + b4.y);
    orow[2*tid+1] = h2pack((v.z - mean)*inv*w4.z + b4.z, (v.w - mean)*inv*w4.w + b4.w);
}

// ---------------- fp16 GEMM core (R6 config): BM=BN=128, BK=64, 8 warps 2x4 ----------------
#define KST 72                       // halves per smem row (144 B)
#define AST_BYTES (128*KST*2)        // 18432
#define STAGE_BYTES (2*AST_BYTES)    // 36864 (A+B)
#define NSTAGE 3
#define GEMM_SMEM (NSTAGE*STAGE_BYTES)   // 110592

__device__ __forceinline__ void issue_tile(uint32_t smu, const __half* A, const __half* B,
                                           int bm, int bn, int K, int k0, int slot)
{
    const int tid = threadIdx.x;
    uint32_t ao = smu + (unsigned)slot * STAGE_BYTES;
    uint32_t bo = ao + AST_BYTES;
    // 128 rows x 64 halves = 1024 chunks of 8 halves (16B) per operand
    #pragma unroll
    for (int c = 0; c < 4; c++) {
        int cid = tid + c * 256;
        int row = cid >> 3;
        int kc  = (cid & 7) * 8;
        cp16(ao + (unsigned)(row*KST + kc)*2, A + (size_t)(bm+row)*K + k0 + kc);
        cp16(bo + (unsigned)(row*KST + kc)*2, B + (size_t)(bn+row)*K + k0 + kc);
    }
}

__device__ __forceinline__ void gemm_main(const __half* __restrict__ A,
                                          const __half* __restrict__ B,
                                          int bm, int bn, int K, uint32_t smu,
                                          float c[4][4][4])
{
    const int tid  = threadIdx.x;
    const int warp = tid >> 5;
    const int lane = tid & 31;
    const int wm = (warp >> 2) * 64;
    const int wn = (warp & 3) * 32;
    const int ar = lane & 15;
    const int ac = (lane >> 4) * 8;
    const int br = (lane & 7) + ((lane >> 4) << 3);
    const int bc = ((lane >> 3) & 1) * 8;

    #pragma unroll
    for (int mt = 0; mt < 4; mt++)
        #pragma unroll
        for (int nt = 0; nt < 4; nt++)
            #pragma unroll
            for (int r = 0; r < 4; r++) c[mt][nt][r] = 0.f;

    const int NT = K >> 6;   // BK = 64
    issue_tile(smu, A, B, bm, bn, K, 0,  0); CP_COMMIT;
    issue_tile(smu, A, B, bm, bn, K, 64, 1); CP_COMMIT;

    for (int kt = 0; kt < NT; kt++) {
        CP_WAIT1;
        __syncthreads();
        if (kt + 2 < NT) issue_tile(smu, A, B, bm, bn, K, (kt+2) << 6, (kt+2) % NSTAGE);
        CP_COMMIT;

        const uint32_t sa = smu + (unsigned)(kt % NSTAGE) * STAGE_BYTES;
        const uint32_t sb = sa + AST_BYTES;

        #pragma unroll
        for (int kc = 0; kc < 4; kc++) {
            uint32_t a[4][4];
            #pragma unroll
            for (int mt = 0; mt < 4; mt++)
                ldsm4(a[mt][0], a[mt][1], a[mt][2], a[mt][3],
                      sa + (unsigned)((wm + mt*16 + ar)*KST + kc*16 + ac) * 2);
            uint32_t bf[4][2];
            #pragma unroll
            for (int p = 0; p < 2; p++) {
                uint32_t r0, r1, r2, r3;
                ldsm4(r0, r1, r2, r3,
                      sb + (unsigned)((wn + p*16 + br)*KST + kc*16 + bc) * 2);
                bf[2*p][0]   = r0; bf[2*p][1]   = r1;
                bf[2*p+1][0] = r2; bf[2*p+1][1] = r3;
            }
            #pragma unroll
            for (int mt = 0; mt < 4; mt++)
                #pragma unroll
                for (int nt = 0; nt < 4; nt++)
                    mma_f16(c[mt][nt], a[mt], bf[nt]);
        }
    }
}

// ---------------- GEMM with fp32 output + residual ----------------
__global__ __launch_bounds__(256, 2)
void gemm_res(const __half* __restrict__ A, const __half* __restrict__ B,
              const float* __restrict__ bias, const float* __restrict__ res,
              float* __restrict__ C, int Nn, int K)
{
    extern __shared__ uint32_t smg[];
    uint32_t smu = (uint32_t)__cvta_generic_to_shared(smg);
    const int bm = blockIdx.y * 128;
    const int bn = blockIdx.x * 128;
    float c[4][4][4];
    gemm_main(A, B, bm, bn, K, smu, c);

    const int tid = threadIdx.x, warp = tid >> 5, lane = tid & 31;
    const int g = lane >> 2, t = lane & 3;
    const int wm = (warp >> 2) * 64, wn = (warp & 3) * 32;
    #pragma unroll
    for (int mt = 0; mt < 4; mt++) {
        #pragma unroll
        for (int nt = 0; nt < 4; nt++) {
            int col = bn + wn + nt * 8 + t * 2;
            float2 bi = *(const float2*)(bias + col);
            #pragma unroll
            for (int h = 0; h < 2; h++) {
                int row = bm + wm + mt * 16 + g + h * 8;
                float2 r = *(const float2*)(res + (size_t)row * Nn + col);
                *(float2*)(C + (size_t)row * Nn + col) =
                    make_float2(c[mt][nt][h*2+0] + bi.x + r.x,
                                c[mt][nt][h*2+1] + bi.y + r.y);
            }
        }
    }
}

// ---------------- GEMM with GELU + fp16 output ----------------
__global__ __launch_bounds__(256, 2)
void gemm_gelu(const __half* __restrict__ A, const __half* __restrict__ B,
               const float* __restrict__ bias, __half* __restrict__ C, int Nn, int K)
{
    extern __shared__ uint32_t smg[];
    uint32_t smu = (uint32_t)__cvta_generic_to_shared(smg);
    const int bm = blockIdx.y * 128;
    const int bn = blockIdx.x * 128;
    float c[4][4][4];
    gemm_main(A, B, bm, bn, K, smu, c);

    const int tid = threadIdx.x, warp = tid >> 5, lane = tid & 31;
    const int g = lane >> 2, t = lane & 3;
    const int wm = (warp >> 2) * 64, wn = (warp & 3) * 32;
    #pragma unroll
    for (int mt = 0; mt < 4; mt++) {
        #pragma unroll
        for (int nt = 0; nt < 4; nt++) {
            int col = bn + wn + nt * 8 + t * 2;
            float2 bi = *(const float2*)(bias + col);
            #pragma unroll
            for (int h = 0; h < 2; h++) {
                int row = bm + wm + mt * 16 + g + h * 8;
                *(uint32_t*)(C + (size_t)row * Nn + col) =
                    h2pack(gelu_exact(c[mt][nt][h*2+0] + bi.x),
                           gelu_exact(c[mt][nt][h*2+1] + bi.y));
            }
        }
    }
}

// ---------------- fused QKV projection (fp16 out, scale on Q) ----------------
__global__ __launch_bounds__(256, 2)
void gemm_qkv(const __half* __restrict__ A,
              const __half* __restrict__ Bq, const __half* __restrict__ Bk, const __half* __restrict__ Bv,
              const float* __restrict__ bq, const float* __restrict__ bk, const float* __restrict__ bv,
              __half* __restrict__ Cq, __half* __restrict__ Ck, __half* __restrict__ Cv, int K)
{
    extern __shared__ uint32_t smg[];
    uint32_t smu = (uint32_t)__cvta_generic_to_shared(smg);
    const int bm  = blockIdx.y * 128;
    const int bng = blockIdx.x * 128;
    const int seg = bng >> 10;
    const int bn  = bng & 1023;
    const __half* B   = (seg == 0) ? Bq : (seg == 1) ? Bk : Bv;
    const float* bias = (seg == 0) ? bq : (seg == 1) ? bk : bv;
    __half*      C    = (seg == 0) ? Cq : (seg == 1) ? Ck : Cv;
    // Q scale = D^-0.5 * log2(e) so attention can use raw ex2 (base-2 softmax)
    const float scale = (seg == 0) ? 0.18033688011112042f : 1.0f;

    float c[4][4][4];
    gemm_main(A, B, bm, bn, K, smu, c);

    const int tid = threadIdx.x, warp = tid >> 5, lane = tid & 31;
    const int g = lane >> 2, t = lane & 3;
    const int wm = (warp >> 2) * 64, wn = (warp & 3) * 32;
    #pragma unroll
    for (int mt = 0; mt < 4; mt++) {
        #pragma unroll
        for (int nt = 0; nt < 4; nt++) {
            int col = bn + wn + nt * 8 + t * 2;
            float2 bi = *(const float2*)(bias + col);
            #pragma unroll
            for (int h = 0; h < 2; h++) {
                int row = bm + wm + mt * 16 + g + h * 8;
                *(uint32_t*)(C + (size_t)row * 1024 + col) =
                    h2pack((c[mt][nt][h*2+0] + bi.x) * scale,
                           (c[mt][nt][h*2+1] + bi.y) * scale);
            }
        }
    }
}

// ---------------- flash attention + fused wo/fc1/fc2 f2h conversion ----------------
// grid.x = QB + CONVX. Blocks x<QB: attention (heavy-first qb remap).
// Blocks x>=QB: grid-stride fp32->fp16 conversion of wo/fc1_w/fc2_w, filling
// idle SM slots of the triangular attention workload. Segment boundaries
// (262144, 1310720) are multiples of the 65536 stride -> warp-uniform.
#define QB_TILES (LL/64)     // 32
#define CONVX 16             // extra x-blocks per y-row -> 512 conv CTAs
#define CONV_TOTAL 2359296   // wo 262144 + w1 1048576 + w2 1048576 (float4)
#define ATST 72   // halves per smem row (144 B)
#define ATT_Q_HALVES (64*ATST)
#define ATT_KV_HALVES (64*ATST)
#define ATT_SMEM ((ATT_Q_HALVES + 4*ATT_KV_HALVES)*2)   // 46080 B

__device__ __forceinline__ void attn_issue_kv(uint32_t smu, const __half* k, const __half* v,
                                              int jb, int n, int hh, int slot)
{
    const int tid = threadIdx.x;   // 0..127
    uint32_t kbase = smu + (unsigned)(ATT_Q_HALVES + slot*2*ATT_KV_HALVES) * 2;
    #pragma unroll
    for (int c = 0; c < 8; c++) {
        int cid = tid + c * 128;
        int sel = cid >> 9;                   // 0=K, 1=V
        int id  = cid & 511;
        int row = id >> 3, c8 = (id & 7) * 8;
        const __half* src = sel ? v : k;
        uint32_t dst = kbase + (unsigned)(sel*ATT_KV_HALVES + row*ATST + c8) * 2;
        cp16(dst, src + ((size_t)((jb*64+row)*NB + n)*EE + hh*DD + c8));
    }
}

__global__ __launch_bounds__(128)
void attn_h(const __half* __restrict__ q, const __half* __restrict__ k,
            const __half* __restrict__ v, __half* __restrict__ o,
            const float4* __restrict__ wo4, const float4* __restrict__ w14,
            const float4* __restrict__ w24,
            uint32_t* __restrict__ dwo, uint32_t* __restrict__ dw1,
            uint32_t* __restrict__ dw2)
{
    const int tid  = threadIdx.x;

    if (blockIdx.x >= QB_TILES) {
        // ---- weight-conversion block ----
        int cid = (blockIdx.x - QB_TILES) + CONVX * blockIdx.y;   // 0..511
        for (int i = cid * 128 + tid; i < CONV_TOTAL; i += CONVX * 32 * 128) {
            const float4* s; uint32_t* d; int local;
            if (i < 262144)       { s = wo4; d = dwo; local = i; }
            else if (i < 1310720) { s = w14; d = dw1; local = i - 262144; }
            else                  { s = w24; d = dw2; local = i - 1310720; }
            float4 vv = s[local];
            *(uint2*)&d[2*local] = make_uint2(h2pack(vv.x, vv.y), h2pack(vv.z, vv.w));
        }
        return;
    }

    extern __shared__ __half smh[];
    const uint32_t smu = (uint32_t)__cvta_generic_to_shared(smh);
    const uint32_t qsu = smu;

    const int qb = QB_TILES - 1 - blockIdx.x;   // heavy-first scheduling
    const int nh = blockIdx.y;
    const int n  = nh / HH;
    const int hh = nh % HH;
    const int warp = tid >> 5;
    const int lane = tid & 31;
    const int g = lane >> 2, t = lane & 3;
    const int m0 = warp * 16;
    const int ar = lane & 15, ac = (lane >> 4) * 8;
    const int br = (lane & 7) + ((lane >> 4) << 3), bc = ((lane >> 3) & 1) * 8;
    const int vr = (lane & 7) + (((lane >> 3) & 1) << 3);
    const int vc = (lane >> 4) * 8;

    // Q tile: 64 rows x 64 halves (pre-scaled by D^-0.5 * log2e)
    #pragma unroll
    for (int p = 0; p < 4; p++) {
        int idx = tid + p * 128;
        int row = idx >> 3, c8 = (idx & 7) * 8;
        *(uint4*)&smh[row*ATST + c8] =
            *(const uint4*)(q + ((size_t)((qb*64+row)*NB + n)*EE + hh*DD + c8));
    }

    attn_issue_kv(smu, k, v, 0, n, hh, 0); CP_COMMIT;

    float l_i[2] = {0.f, 0.f};
    float accO[8][4];
    #pragma unroll
    for (int dt = 0; dt < 8; dt++)
        #pragma unroll
        for (int r = 0; r < 4; r++) accO[dt][r] = 0.f;

    for (int jb = 0; jb <= qb; jb++) {
        if (jb + 1 <= qb) attn_issue_kv(smu, k, v, jb+1, n, hh, (jb+1) & 1);
        CP_COMMIT;
        CP_WAIT1;
        __syncthreads();

        const uint32_t ksu = smu + (unsigned)(ATT_Q_HALVES + (jb & 1)*2*ATT_KV_HALVES) * 2;
        const uint32_t vsu = ksu + (unsigned)ATT_KV_HALVES * 2;

        // S' = (log2e/sqrt(D)) * Q K^T (16 x 64 per warp)
        float sc[8][4];
        #pragma unroll
        for (int nt = 0; nt < 8; nt++)
            #pragma unroll
            for (int r = 0; r < 4; r++) sc[nt][r] = 0.f;

        #pragma unroll
        for (int kc = 0; kc < 4; kc++) {
            uint32_t a[4];
            ldsm4(a[0], a[1], a[2], a[3],
                  qsu + (unsigned)((m0 + ar)*ATST + kc*16 + ac) * 2);
            #pragma unroll
            for (int p = 0; p < 4; p++) {
                uint32_t r0, r1, r2, r3;
                ldsm4(r0, r1, r2, r3,
                      ksu + (unsigned)((p*16 + br)*ATST + kc*16 + bc) * 2);
                uint32_t b0[2] = {r0, r1}, b1[2] = {r2, r3};
                mma_f16(sc[2*p],   a, b0);
                mma_f16(sc[2*p+1], a, b1);
            }
        }

        // causal mask on diagonal tile
        if (jb == qb) {
            int r0 = m0 + g, r1 = m0 + g + 8;
            #pragma unroll
            for (int nt = 0; nt < 8; nt++) {
                int col = nt * 8 + t * 2;
                if (col     > r0) sc[nt][0] = -1e30f;
                if (col + 1 > r0) sc[nt][1] = -1e30f;
                if (col     > r1) sc[nt][2] = -1e30f;
                if (col + 1 > r1) sc[nt][3] = -1e30f;
            }
        }

        // fixed-reference softmax: p = 2^{S'}; accumulate row sums (quad-reduced)
        float sum0 = 0.f, sum1 = 0.f;
        #pragma unroll
        for (int nt = 0; nt < 8; nt++) {
            sc[nt][0] = fexp2(sc[nt][0]); sum0 += sc[nt][0];
            sc[nt][1] = fexp2(sc[nt][1]); sum0 += sc[nt][1];
            sc[nt][2] = fexp2(sc[nt][2]); sum1 += sc[nt][2];
            sc[nt][3] = fexp2(sc[nt][3]); sum1 += sc[nt][3];
        }
        #pragma unroll
        for (int off = 1; off < 4; off <<= 1) {
            sum0 += __shfl_xor_sync(0xffffffffu, sum0, off);
            sum1 += __shfl_xor_sync(0xffffffffu, sum1, off);
        }
        l_i[0] += sum0;
        l_i[1] += sum1;

        // O += P V (S C-frag == P A-frag; V B-frags via ldsm.trans)
        #pragma unroll
        for (int kc = 0; kc < 4; kc++) {
            uint32_t a[4];
            a[0] = h2pack(sc[2*kc][0],   sc[2*kc][1]);
            a[1] = h2pack(sc[2*kc][2],   sc[2*kc][3]);
            a[2] = h2pack(sc[2*kc+1][0], sc[2*kc+1][1]);
            a[3] = h2pack(sc[2*kc+1][2], sc[2*kc+1][3]);
            #pragma unroll
            for (int dp = 0; dp < 4; dp++) {
                uint32_t r0, r1, r2, r3;
                ldsm4t(r0, r1, r2, r3,
                       vsu + (unsigned)((kc*16 + vr)*ATST + dp*16 + vc) * 2);
                uint32_t b0[2] = {r0, r1}, b1[2] = {r2, r3};
                mma_f16(accO[2*dp],   a, b0);
                mma_f16(accO[2*dp+1], a, b1);
            }
        }
        __syncthreads();
    }

    // normalize + store fp16
    float inv0 = 1.0f / l_i[0], inv1 = 1.0f / l_i[1];
    int l0 = qb*64 + m0 + g;
    int l1 = l0 + 8;
    #pragma unroll
    for (int dt = 0; dt < 8; dt++) {
        int d = hh*DD + dt*8 + t*2;
        *(uint32_t*)(o + ((size_t)(l0*NB + n)*EE + d)) =
            h2pack(accO[dt][0]*inv0, accO[dt][1]*inv0);
        *(uint32_t*)(o + ((size_t)(l1*NB + n)*EE + d)) =
            h2pack(accO[dt][2]*inv1, accO[dt][3]*inv1);
    }
}

// ---------------- launch ----------------
extern "C" void kernel_launch(void* const* d_in, const int* in_sizes, int n_in,
                              void* d_out, int out_size)
{
    const float* x     = (const float*)d_in[0];
    const float* ln1_w = (const float*)d_in[1];
    const float* ln1_b = (const float*)d_in[2];
    const float* wq    = (const float*)d_in[3];
    const float* bq    = (const float*)d_in[4];
    const float* wk    = (const float*)d_in[5];
    const float* bk    = (const float*)d_in[6];
    const float* wv    = (const float*)d_in[7];
    const float* bv    = (const float*)d_in[8];
    const float* wout  = (const float*)d_in[9];
    const float* bout  = (const float*)d_in[10];
    const float* ln2_w = (const float*)d_in[11];
    const float* ln2_b = (const float*)d_in[12];
    const float* fc1_w = (const float*)d_in[13];
    const float* fc1_b = (const float*)d_in[14];
    const float* fc2_w = (const float*)d_in[15];
    const float* fc2_b = (const float*)d_in[16];
    float* out = (float*)d_out;

    __half *h, *q, *k, *v, *o, *h2, *mid;
    __half *cwq, *cwk, *cwv, *cwo, *cw1, *cw2;
    float  *x2;
    cudaGetSymbolAddress((void**)&h,   g_h);
    cudaGetSymbolAddress((void**)&q,   g_q);
    cudaGetSymbolAddress((void**)&k,   g_k);
    cudaGetSymbolAddress((void**)&v,   g_v);
    cudaGetSymbolAddress((void**)&o,   g_o);
    cudaGetSymbolAddress((void**)&h2,  g_h2);
    cudaGetSymbolAddress((void**)&mid, g_mid);
    cudaGetSymbolAddress((void**)&x2,  g_x2);
    cudaGetSymbolAddress((void**)&cwq, g_wq);
    cudaGetSymbolAddress((void**)&cwk, g_wk);
    cudaGetSymbolAddress((void**)&cwv, g_wv);
    cudaGetSymbolAddress((void**)&cwo, g_wo);
    cudaGetSymbolAddress((void**)&cw1, g_w1);
    cudaGetSymbolAddress((void**)&cw2, g_w2);

    cudaFuncSetAttribute(gemm_qkv,  cudaFuncAttributeMaxDynamicSharedMemorySize, GEMM_SMEM);
    cudaFuncSetAttribute(gemm_res,  cudaFuncAttributeMaxDynamicSharedMemorySize, GEMM_SMEM);
    cudaFuncSetAttribute(gemm_gelu, cudaFuncAttributeMaxDynamicSharedMemorySize, GEMM_SMEM);
    cudaFuncSetAttribute(attn_h,    cudaFuncAttributeMaxDynamicSharedMemorySize, ATT_SMEM);

    // f2h of QKV weights only (the rest converts inside the attention launch)
    f2h_qkv<<<3072, 256>>>((const float4*)wq, (const float4*)wk, (const float4*)wv,
                           (uint32_t*)cwq, (uint32_t*)cwk, (uint32_t*)cwv);

    // LN1: x -> h (fp16)
    ln_kernel<<<ROWS, 256>>>(x, ln1_w, ln1_b, h);

    // fused QKV (M=4096, N=3*1024, K=1024); D^-0.5*log2e folded into Q
    dim3 gqkv(3 * EE / 128, ROWS / 128);
    gemm_qkv<<<gqkv, 256, GEMM_SMEM>>>(h, cwq, cwk, cwv, bq, bk, bv, q, k, v, EE);

    // causal flash attention + fused wo/fc1/fc2 weight conversion
    dim3 ga(QB_TILES + CONVX, NB * HH);
    attn_h<<<ga, 128, ATT_SMEM>>>(q, k, v, o,
                                  (const float4*)wout, (const float4*)fc1_w,
                                  (const float4*)fc2_w,
                                  (uint32_t*)cwo, (uint32_t*)cw1, (uint32_t*)cw2);

    // out projection + residual(x) -> x2 (fp32)
    dim3 g1024(EE / 128, ROWS / 128);
    gemm_res<<<g1024, 256, GEMM_SMEM>>>(o, cwo, bout, x, x2, EE, EE);

    // LN2: x2 -> h2 (fp16)
    ln_kernel<<<ROWS, 256>>>(x2, ln2_w, ln2_b, h2);

    // FC1 + GELU -> mid (fp16)
    dim3 g4096(FF / 128, ROWS / 128);
    gemm_gelu<<<g4096, 256, GEMM_SMEM>>>(h2, cw1, fc1_b, mid, FF, EE);

    // FC2 + residual(x2) -> out (fp32)
    gemm_res<<<g1024, 256, GEMM_SMEM>>>(mid, cw2, fc2_b, x2, out, EE, FF);
}

// round 16
// speedup vs baseline: 1.0378x; 1.0378x over previous
#include <cuda_runtime.h>
#include <cuda_fp16.h>
#include <math.h>
#include <stdint.h>

// Problem constants
#define LL 2048
#define NB 2
#define EE 1024
#define HH 16
#define DD 64
#define FF 4096
#define ROWS (LL*NB)   // 4096

// ---------------- scratch (no allocation allowed) ----------------
__device__ __half g_h  [ROWS*EE];
__device__ __half g_q  [ROWS*EE];
__device__ __half g_k  [ROWS*EE];
__device__ __half g_v  [ROWS*EE];
__device__ __half g_o  [ROWS*EE];
__device__ __half g_h2 [ROWS*EE];
__device__ __half g_mid[(size_t)ROWS*FF];
__device__ float  g_x2 [ROWS*EE];
// fp16 weight copies
__device__ __half g_wq [EE*EE];
__device__ __half g_wk [EE*EE];
__device__ __half g_wv [EE*EE];
__device__ __half g_wo [EE*EE];
__device__ __half g_w1 [FF*EE];
__device__ __half g_w2 [EE*FF];

// ---------------- helpers ----------------
__device__ __forceinline__ uint32_t h2pack(float a, float b) {
    __half2 h = __floats2half2_rn(a, b);
    return *reinterpret_cast<uint32_t*>(&h);
}
__device__ __forceinline__ float fexp2(float x) {
    float y;
    asm("ex2.approx.ftz.f32 %0, %1;" : "=f"(y) : "f"(x));
    return y;
}
__device__ __forceinline__ void mma_f16(float* c, const uint32_t* a, const uint32_t* b) {
    asm volatile(
        "mma.sync.aligned.m16n8k16.row.col.f32.f16.f16.f32 "
        "{%0,%1,%2,%3}, {%4,%5,%6,%7}, {%8,%9}, {%0,%1,%2,%3};\n"
        : "+f"(c[0]), "+f"(c[1]), "+f"(c[2]), "+f"(c[3])
        : "r"(a[0]), "r"(a[1]), "r"(a[2]), "r"(a[3]), "r"(b[0]), "r"(b[1]));
}
__device__ __forceinline__ void ldsm4(uint32_t& r0, uint32_t& r1, uint32_t& r2, uint32_t& r3,
                                      uint32_t addr) {
    asm volatile("ldmatrix.sync.aligned.m8n8.x4.shared.b16 {%0,%1,%2,%3}, [%4];\n"
                 : "=r"(r0), "=r"(r1), "=r"(r2), "=r"(r3) : "r"(addr));
}
__device__ __forceinline__ void ldsm4t(uint32_t& r0, uint32_t& r1, uint32_t& r2, uint32_t& r3,
                                       uint32_t addr) {
    asm volatile("ldmatrix.sync.aligned.m8n8.x4.trans.shared.b16 {%0,%1,%2,%3}, [%4];\n"
                 : "=r"(r0), "=r"(r1), "=r"(r2), "=r"(r3) : "r"(addr));
}
__device__ __forceinline__ void cp16(uint32_t saddr, const void* g) {
    asm volatile("cp.async.cg.shared.global [%0], [%1], 16;\n" :: "r"(saddr), "l"(g));
}
#define CP_COMMIT asm volatile("cp.async.commit_group;\n")
#define CP_WAIT1  asm volatile("cp.async.wait_group 1;\n")

__device__ __forceinline__ float gelu_exact(float t) {
    return 0.5f * t * (1.0f + erff(t * 0.70710678118654752f));
}

// ---------------- f2h for QKV weights only (needed before QKV GEMM) ----------------
__global__ __launch_bounds__(256)
void f2h_qkv(const float4* __restrict__ wq, const float4* __restrict__ wk,
             const float4* __restrict__ wv,
             uint32_t* __restrict__ dq, uint32_t* __restrict__ dk,
             uint32_t* __restrict__ dv)
{
    int i = blockIdx.x * 256 + threadIdx.x;   // 0 .. 786431
    const float4* s; uint32_t* d; int local;
    if (i < 262144)      { s = wq; d = dq; local = i; }
    else if (i < 524288) { s = wk; d = dk; local = i - 262144; }
    else                 { s = wv; d = dv; local = i - 524288; }
    float4 v = s[local];
    *(uint2*)&d[2*local] = make_uint2(h2pack(v.x, v.y), h2pack(v.z, v.w));
}

// ---------------- LayerNorm: fp32 in, fp16 out ----------------
__global__ __launch_bounds__(256)
void ln_kernel(const float* __restrict__ x, const float* __restrict__ w,
               const float* __restrict__ b, __half* __restrict__ out)
{
    int row = blockIdx.x;
    int tid = threadIdx.x;
    const float4* xr = (const float4*)(x + (size_t)row * EE);
    float4 v = xr[tid];
    float s  = v.x + v.y + v.z + v.w;
    float ss = v.x*v.x + v.y*v.y + v.z*v.z + v.w*v.w;
    #pragma unroll
    for (int o = 16; o > 0; o >>= 1) {
        s  += __shfl_xor_sync(0xffffffffu, s,  o);
        ss += __shfl_xor_sync(0xffffffffu, ss, o);
    }
    __shared__ float sbuf[8], ssbuf[8];
    if ((tid & 31) == 0) { sbuf[tid >> 5] = s; ssbuf[tid >> 5] = ss; }
    __syncthreads();
    float ts = 0.f, tss = 0.f;
    #pragma unroll
    for (int i = 0; i < 8; i++) { ts += sbuf[i]; tss += ssbuf[i]; }
    float mean = ts * (1.0f / EE);
    float var  = tss * (1.0f / EE) - mean * mean;
    float inv  = rsqrtf(var + 1e-5f);
    float4 w4 = ((const float4*)w)[tid];
    float4 b4 = ((const float4*)b)[tid];
    uint32_t* orow = (uint32_t*)(out + (size_t)row * EE);
    orow[2*tid]   = h2pack((v.x - mean)*inv*w4.x + b4.x, (v.y - mean)*inv*w4.y + b4.y);
    orow[2*tid+1] = h2pack((v.z - mean)*inv*w4.z + b4.z, (v.w - mean)*inv*w4.w + b4.w);
}

// ---------------- fp16 GEMM core (R6 config): BM=BN=128, BK=64, 8 warps 2x4 ----------------
#define KST 72                       // halves per smem row (144 B)
#define AST_BYTES (128*KST*2)        // 18432
#define STAGE_BYTES (2*AST_BYTES)    // 36864 (A+B)
#define NSTAGE 3
#define GEMM_SMEM (NSTAGE*STAGE_BYTES)   // 110592

__device__ __forceinline__ void issue_tile(uint32_t smu, const __half* A, const __half* B,
                                           int bm, int bn, int K, int k0, int slot)
{
    const int tid = threadIdx.x;
    uint32_t ao = smu + (unsigned)slot * STAGE_BYTES;
    uint32_t bo = ao + AST_BYTES;
    // 128 rows x 64 halves = 1024 chunks of 8 halves (16B) per operand
    #pragma unroll
    for (int c = 0; c < 4; c++) {
        int cid = tid + c * 256;
        int row = cid >> 3;
        int kc  = (cid & 7) * 8;
        cp16(ao + (unsigned)(row*KST + kc)*2, A + (size_t)(bm+row)*K + k0 + kc);
        cp16(bo + (unsigned)(row*KST + kc)*2, B + (size_t)(bn+row)*K + k0 + kc);
    }
}

__device__ __forceinline__ void gemm_main(const __half* __restrict__ A,
                                          const __half* __restrict__ B,
                                          int bm, int bn, int K, uint32_t smu,
                                          float c[4][4][4])
{
    const int tid  = threadIdx.x;
    const int warp = tid >> 5;
    const int lane = tid & 31;
    const int wm = (warp >> 2) * 64;
    const int wn = (warp & 3) * 32;
    const int ar = lane & 15;
    const int ac = (lane >> 4) * 8;
    const int br = (lane & 7) + ((lane >> 4) << 3);
    const int bc = ((lane >> 3) & 1) * 8;

    #pragma unroll
    for (int mt = 0; mt < 4; mt++)
        #pragma unroll
        for (int nt = 0; nt < 4; nt++)
            #pragma unroll
            for (int r = 0; r < 4; r++) c[mt][nt][r] = 0.f;

    const int NT = K >> 6;   // BK = 64
    issue_tile(smu, A, B, bm, bn, K, 0,  0); CP_COMMIT;
    issue_tile(smu, A, B, bm, bn, K, 64, 1); CP_COMMIT;

    for (int kt = 0; kt < NT; kt++) {
        CP_WAIT1;
        __syncthreads();
        if (kt + 2 < NT) issue_tile(smu, A, B, bm, bn, K, (kt+2) << 6, (kt+2) % NSTAGE);
        CP_COMMIT;

        const uint32_t sa = smu + (unsigned)(kt % NSTAGE) * STAGE_BYTES;
        const uint32_t sb = sa + AST_BYTES;

        #pragma unroll
        for (int kc = 0; kc < 4; kc++) {
            uint32_t a[4][4];
            #pragma unroll
            for (int mt = 0; mt < 4; mt++)
                ldsm4(a[mt][0], a[mt][1], a[mt][2], a[mt][3],
                      sa + (unsigned)((wm + mt*16 + ar)*KST + kc*16 + ac) * 2);
            uint32_t bf[4][2];
            #pragma unroll
            for (int p = 0; p < 2; p++) {
                uint32_t r0, r1, r2, r3;
                ldsm4(r0, r1, r2, r3,
                      sb + (unsigned)((wn + p*16 + br)*KST + kc*16 + bc) * 2);
                bf[2*p][0]   = r0; bf[2*p][1]   = r1;
                bf[2*p+1][0] = r2; bf[2*p+1][1] = r3;
            }
            #pragma unroll
            for (int mt = 0; mt < 4; mt++)
                #pragma unroll
                for (int nt = 0; nt < 4; nt++)
                    mma_f16(c[mt][nt], a[mt], bf[nt]);
        }
    }
}

// ---------------- GEMM with fp32 output + residual ----------------
__global__ __launch_bounds__(256, 2)
void gemm_res(const __half* __restrict__ A, const __half* __restrict__ B,
              const float* __restrict__ bias, const float* __restrict__ res,
              float* __restrict__ C, int Nn, int K)
{
    extern __shared__ uint32_t smg[];
    uint32_t smu = (uint32_t)__cvta_generic_to_shared(smg);
    const int bm = blockIdx.y * 128;
    const int bn = blockIdx.x * 128;
    float c[4][4][4];
    gemm_main(A, B, bm, bn, K, smu, c);

    const int tid = threadIdx.x, warp = tid >> 5, lane = tid & 31;
    const int g = lane >> 2, t = lane & 3;
    const int wm = (warp >> 2) * 64, wn = (warp & 3) * 32;
    #pragma unroll
    for (int mt = 0; mt < 4; mt++) {
        #pragma unroll
        for (int nt = 0; nt < 4; nt++) {
            int col = bn + wn + nt * 8 + t * 2;
            float2 bi = *(const float2*)(bias + col);
            #pragma unroll
            for (int h = 0; h < 2; h++) {
                int row = bm + wm + mt * 16 + g + h * 8;
                float2 r = *(const float2*)(res + (size_t)row * Nn + col);
                *(float2*)(C + (size_t)row * Nn + col) =
                    make_float2(c[mt][nt][h*2+0] + bi.x + r.x,
                                c[mt][nt][h*2+1] + bi.y + r.y);
            }
        }
    }
}

// ---------------- GEMM with GELU + fp16 output ----------------
__global__ __launch_bounds__(256, 2)
void gemm_gelu(const __half* __restrict__ A, const __half* __restrict__ B,
               const float* __restrict__ bias, __half* __restrict__ C, int Nn, int K)
{
    extern __shared__ uint32_t smg[];
    uint32_t smu = (uint32_t)__cvta_generic_to_shared(smg);
    const int bm = blockIdx.y * 128;
    const int bn = blockIdx.x * 128;
    float c[4][4][4];
    gemm_main(A, B, bm, bn, K, smu, c);

    const int tid = threadIdx.x, warp = tid >> 5, lane = tid & 31;
    const int g = lane >> 2, t = lane & 3;
    const int wm = (warp >> 2) * 64, wn = (warp & 3) * 32;
    #pragma unroll
    for (int mt = 0; mt < 4; mt++) {
        #pragma unroll
        for (int nt = 0; nt < 4; nt++) {
            int col = bn + wn + nt * 8 + t * 2;
            float2 bi = *(const float2*)(bias + col);
            #pragma unroll
            for (int h = 0; h < 2; h++) {
                int row = bm + wm + mt * 16 + g + h * 8;
                *(uint32_t*)(C + (size_t)row * Nn + col) =
                    h2pack(gelu_exact(c[mt][nt][h*2+0] + bi.x),
                           gelu_exact(c[mt][nt][h*2+1] + bi.y));
            }
        }
    }
}

// ---------------- fused QKV projection (fp16 out, scale on Q) ----------------
__global__ __launch_bounds__(256, 2)
void gemm_qkv(const __half* __restrict__ A,
              const __half* __restrict__ Bq, const __half* __restrict__ Bk, const __half* __restrict__ Bv,
              const float* __restrict__ bq, const float* __restrict__ bk, const float* __restrict__ bv,
              __half* __restrict__ Cq, __half* __restrict__ Ck, __half* __restrict__ Cv, int K)
{
    extern __shared__ uint32_t smg[];
    uint32_t smu = (uint32_t)__cvta_generic_to_shared(smg);
    const int bm  = blockIdx.y * 128;
    const int bng = blockIdx.x * 128;
    const int seg = bng >> 10;
    const int bn  = bng & 1023;
    const __half* B   = (seg == 0) ? Bq : (seg == 1) ? Bk : Bv;
    const float* bias = (seg == 0) ? bq : (seg == 1) ? bk : bv;
    __half*      C    = (seg == 0) ? Cq : (seg == 1) ? Ck : Cv;
    // Q scale = D^-0.5 * log2(e) so attention can use raw ex2 (base-2 softmax)
    const float scale = (seg == 0) ? 0.18033688011112042f : 1.0f;

    float c[4][4][4];
    gemm_main(A, B, bm, bn, K, smu, c);

    const int tid = threadIdx.x, warp = tid >> 5, lane = tid & 31;
    const int g = lane >> 2, t = lane & 3;
    const int wm = (warp >> 2) * 64, wn = (warp & 3) * 32;
    #pragma unroll
    for (int mt = 0; mt < 4; mt++) {
        #pragma unroll
        for (int nt = 0; nt < 4; nt++) {
            int col = bn + wn + nt * 8 + t * 2;
            float2 bi = *(const float2*)(bias + col);
            #pragma unroll
            for (int h = 0; h < 2; h++) {
                int row = bm + wm + mt * 16 + g + h * 8;
                *(uint32_t*)(C + (size_t)row * 1024 + col) =
                    h2pack((c[mt][nt][h*2+0] + bi.x) * scale,
                           (c[mt][nt][h*2+1] + bi.y) * scale);
            }
        }
    }
}

// ---------------- flash attention + TAIL-placed wo/fc1/fc2 f2h conversion ----------------
// 1D grid of ATT_BLOCKS + CONV_BLOCKS. Blocks [0, ATT_BLOCKS): attention with
// the exact R14 ordering (bid&31 -> heavy-first qb, bid>>5 -> head). Blocks
// [ATT_BLOCKS, +CONV_BLOCKS): weight conversion — launched LAST, so they only
// backfill SM slots as the triangular attention load tapers.
#define QB_TILES (LL/64)                 // 32
#define ATT_BLOCKS (QB_TILES * NB * HH)  // 1024
#define CONV_BLOCKS 512
#define CONV_TOTAL 2359296   // wo 262144 + w1 1048576 + w2 1048576 (float4)
#define ATST 72   // halves per smem row (144 B)
#define ATT_Q_HALVES (64*ATST)
#define ATT_KV_HALVES (64*ATST)
#define ATT_SMEM ((ATT_Q_HALVES + 4*ATT_KV_HALVES)*2)   // 46080 B

__device__ __forceinline__ void attn_issue_kv(uint32_t smu, const __half* k, const __half* v,
                                              int jb, int n, int hh, int slot)
{
    const int tid = threadIdx.x;   // 0..127
    uint32_t kbase = smu + (unsigned)(ATT_Q_HALVES + slot*2*ATT_KV_HALVES) * 2;
    #pragma unroll
    for (int c = 0; c < 8; c++) {
        int cid = tid + c * 128;
        int sel = cid >> 9;                   // 0=K, 1=V
        int id  = cid & 511;
        int row = id >> 3, c8 = (id & 7) * 8;
        const __half* src = sel ? v : k;
        uint32_t dst = kbase + (unsigned)(sel*ATT_KV_HALVES + row*ATST + c8) * 2;
        cp16(dst, src + ((size_t)((jb*64+row)*NB + n)*EE + hh*DD + c8));
    }
}

__global__ __launch_bounds__(128, 4)
void attn_h(const __half* __restrict__ q, const __half* __restrict__ k,
            const __half* __restrict__ v, __half* __restrict__ o,
            const float4* __restrict__ wo4, const float4* __restrict__ w14,
            const float4* __restrict__ w24,
            uint32_t* __restrict__ dwo, uint32_t* __restrict__ dw1,
            uint32_t* __restrict__ dw2)
{
    const int tid = threadIdx.x;
    const int bid = blockIdx.x;

    if (bid >= ATT_BLOCKS) {
        // ---- weight-conversion block (tail of launch order) ----
        int cid = bid - ATT_BLOCKS;                    // 0..511
        for (int i = cid * 128 + tid; i < CONV_TOTAL; i += CONV_BLOCKS * 128) {
            const float4* s; uint32_t* d; int local;
            if (i < 262144)       { s = wo4; d = dwo; local = i; }
            else if (i < 1310720) { s = w14; d = dw1; local = i - 262144; }
            else                  { s = w24; d = dw2; local = i - 1310720; }
            float4 vv = s[local];
            *(uint2*)&d[2*local] = make_uint2(h2pack(vv.x, vv.y), h2pack(vv.z, vv.w));
        }
        return;
    }

    extern __shared__ __half smh[];
    const uint32_t smu = (uint32_t)__cvta_generic_to_shared(smh);
    const uint32_t qsu = smu;

    const int qb = QB_TILES - 1 - (bid & (QB_TILES - 1));   // heavy-first
    const int nh = bid >> 5;
    const int n  = nh / HH;
    const int hh = nh % HH;
    const int warp = tid >> 5;
    const int lane = tid & 31;
    const int g = lane >> 2, t = lane & 3;
    const int m0 = warp * 16;
    const int ar = lane & 15, ac = (lane >> 4) * 8;
    const int br = (lane & 7) + ((lane >> 4) << 3), bc = ((lane >> 3) & 1) * 8;
    const int vr = (lane & 7) + (((lane >> 3) & 1) << 3);
    const int vc = (lane >> 4) * 8;

    // Q tile: 64 rows x 64 halves (pre-scaled by D^-0.5 * log2e)
    #pragma unroll
    for (int p = 0; p < 4; p++) {
        int idx = tid + p * 128;
        int row = idx >> 3, c8 = (idx & 7) * 8;
        *(uint4*)&smh[row*ATST + c8] =
            *(const uint4*)(q + ((size_t)((qb*64+row)*NB + n)*EE + hh*DD + c8));
    }

    attn_issue_kv(smu, k, v, 0, n, hh, 0); CP_COMMIT;

    float l_i[2] = {0.f, 0.f};
    float accO[8][4];
    #pragma unroll
    for (int dt = 0; dt < 8; dt++)
        #pragma unroll
        for (int r = 0; r < 4; r++) accO[dt][r] = 0.f;

    for (int jb = 0; jb <= qb; jb++) {
        if (jb + 1 <= qb) attn_issue_kv(smu, k, v, jb+1, n, hh, (jb+1) & 1);
        CP_COMMIT;
        CP_WAIT1;
        __syncthreads();

        const uint32_t ksu = smu + (unsigned)(ATT_Q_HALVES + (jb & 1)*2*ATT_KV_HALVES) * 2;
        const uint32_t vsu = ksu + (unsigned)ATT_KV_HALVES * 2;

        // S' = (log2e/sqrt(D)) * Q K^T (16 x 64 per warp)
        float sc[8][4];
        #pragma unroll
        for (int nt = 0; nt < 8; nt++)
            #pragma unroll
            for (int r = 0; r < 4; r++) sc[nt][r] = 0.f;

        #pragma unroll
        for (int kc = 0; kc < 4; kc++) {
            uint32_t a[4];
            ldsm4(a[0], a[1], a[2], a[3],
                  qsu + (unsigned)((m0 + ar)*ATST + kc*16 + ac) * 2);
            #pragma unroll
            for (int p = 0; p < 4; p++) {
                uint32_t r0, r1, r2, r3;
                ldsm4(r0, r1, r2, r3,
                      ksu + (unsigned)((p*16 + br)*ATST + kc*16 + bc) * 2);
                uint32_t b0[2] = {r0, r1}, b1[2] = {r2, r3};
                mma_f16(sc[2*p],   a, b0);
                mma_f16(sc[2*p+1], a, b1);
            }
        }

        // causal mask on diagonal tile
        if (jb == qb) {
            int r0 = m0 + g, r1 = m0 + g + 8;
            #pragma unroll
            for (int nt = 0; nt < 8; nt++) {
                int col = nt * 8 + t * 2;
                if (col     > r0) sc[nt][0] = -1e30f;
                if (col + 1 > r0) sc[nt][1] = -1e30f;
                if (col     > r1) sc[nt][2] = -1e30f;
                if (col + 1 > r1) sc[nt][3] = -1e30f;
            }
        }

        // fixed-reference softmax: p = 2^{S'}; accumulate row sums (quad-reduced)
        float sum0 = 0.f, sum1 = 0.f;
        #pragma unroll
        for (int nt = 0; nt < 8; nt++) {
            sc[nt][0] = fexp2(sc[nt][0]); sum0 += sc[nt][0];
            sc[nt][1] = fexp2(sc[nt][1]); sum0 += sc[nt][1];
            sc[nt][2] = fexp2(sc[nt][2]); sum1 += sc[nt][2];
            sc[nt][3] = fexp2(sc[nt][3]); sum1 += sc[nt][3];
        }
        #pragma unroll
        for (int off = 1; off < 4; off <<= 1) {
            sum0 += __shfl_xor_sync(0xffffffffu, sum0, off);
            sum1 += __shfl_xor_sync(0xffffffffu, sum1, off);
        }
        l_i[0] += sum0;
        l_i[1] += sum1;

        // O += P V (S C-frag == P A-frag; V B-frags via ldsm.trans)
        #pragma unroll
        for (int kc = 0; kc < 4; kc++) {
            uint32_t a[4];
            a[0] = h2pack(sc[2*kc][0],   sc[2*kc][1]);
            a[1] = h2pack(sc[2*kc][2],   sc[2*kc][3]);
            a[2] = h2pack(sc[2*kc+1][0], sc[2*kc+1][1]);
            a[3] = h2pack(sc[2*kc+1][2], sc[2*kc+1][3]);
            #pragma unroll
            for (int dp = 0; dp < 4; dp++) {
                uint32_t r0, r1, r2, r3;
                ldsm4t(r0, r1, r2, r3,
                       vsu + (unsigned)((kc*16 + vr)*ATST + dp*16 + vc) * 2);
                uint32_t b0[2] = {r0, r1}, b1[2] = {r2, r3};
                mma_f16(accO[2*dp],   a, b0);
                mma_f16(accO[2*dp+1], a, b1);
            }
        }
        __syncthreads();
    }

    // normalize + store fp16
    float inv0 = 1.0f / l_i[0], inv1 = 1.0f / l_i[1];
    int l0 = qb*64 + m0 + g;
    int l1 = l0 + 8;
    #pragma unroll
    for (int dt = 0; dt < 8; dt++) {
        int d = hh*DD + dt*8 + t*2;
        *(uint32_t*)(o + ((size_t)(l0*NB + n)*EE + d)) =
            h2pack(accO[dt][0]*inv0, accO[dt][1]*inv0);
        *(uint32_t*)(o + ((size_t)(l1*NB + n)*EE + d)) =
            h2pack(accO[dt][2]*inv1, accO[dt][3]*inv1);
    }
}

// ---------------- launch ----------------
extern "C" void kernel_launch(void* const* d_in, const int* in_sizes, int n_in,
                              void* d_out, int out_size)
{
    const float* x     = (const float*)d_in[0];
    const float* ln1_w = (const float*)d_in[1];
    const float* ln1_b = (const float*)d_in[2];
    const float* wq    = (const float*)d_in[3];
    const float* bq    = (const float*)d_in[4];
    const float* wk    = (const float*)d_in[5];
    const float* bk    = (const float*)d_in[6];
    const float* wv    = (const float*)d_in[7];
    const float* bv    = (const float*)d_in[8];
    const float* wout  = (const float*)d_in[9];
    const float* bout  = (const float*)d_in[10];
    const float* ln2_w = (const float*)d_in[11];
    const float* ln2_b = (const float*)d_in[12];
    const float* fc1_w = (const float*)d_in[13];
    const float* fc1_b = (const float*)d_in[14];
    const float* fc2_w = (const float*)d_in[15];
    const float* fc2_b = (const float*)d_in[16];
    float* out = (float*)d_out;

    __half *h, *q, *k, *v, *o, *h2, *mid;
    __half *cwq, *cwk, *cwv, *cwo, *cw1, *cw2;
    float  *x2;
    cudaGetSymbolAddress((void**)&h,   g_h);
    cudaGetSymbolAddress((void**)&q,   g_q);
    cudaGetSymbolAddress((void**)&k,   g_k);
    cudaGetSymbolAddress((void**)&v,   g_v);
    cudaGetSymbolAddress((void**)&o,   g_o);
    cudaGetSymbolAddress((void**)&h2,  g_h2);
    cudaGetSymbolAddress((void**)&mid, g_mid);
    cudaGetSymbolAddress((void**)&x2,  g_x2);
    cudaGetSymbolAddress((void**)&cwq, g_wq);
    cudaGetSymbolAddress((void**)&cwk, g_wk);
    cudaGetSymbolAddress((void**)&cwv, g_wv);
    cudaGetSymbolAddress((void**)&cwo, g_wo);
    cudaGetSymbolAddress((void**)&cw1, g_w1);
    cudaGetSymbolAddress((void**)&cw2, g_w2);

    cudaFuncSetAttribute(gemm_qkv,  cudaFuncAttributeMaxDynamicSharedMemorySize, GEMM_SMEM);
    cudaFuncSetAttribute(gemm_res,  cudaFuncAttributeMaxDynamicSharedMemorySize, GEMM_SMEM);
    cudaFuncSetAttribute(gemm_gelu, cudaFuncAttributeMaxDynamicSharedMemorySize, GEMM_SMEM);
    cudaFuncSetAttribute(attn_h,    cudaFuncAttributeMaxDynamicSharedMemorySize, ATT_SMEM);

    // f2h of QKV weights only (the rest converts inside the attention launch)
    f2h_qkv<<<3072, 256>>>((const float4*)wq, (const float4*)wk, (const float4*)wv,
                           (uint32_t*)cwq, (uint32_t*)cwk, (uint32_t*)cwv);

    // LN1: x -> h (fp16)
    ln_kernel<<<ROWS, 256>>>(x, ln1_w, ln1_b, h);

    // fused QKV (M=4096, N=3*1024, K=1024); D^-0.5*log2e folded into Q
    dim3 gqkv(3 * EE / 128, ROWS / 128);
    gemm_qkv<<<gqkv, 256, GEMM_SMEM>>>(h, cwq, cwk, cwv, bq, bk, bv, q, k, v, EE);

    // causal flash attention (R14 ordering) + tail-placed wo/fc1/fc2 conversion
    attn_h<<<ATT_BLOCKS + CONV_BLOCKS, 128, ATT_SMEM>>>(
        q, k, v, o,
        (const float4*)wout, (const float4*)fc1_w, (const float4*)fc2_w,
        (uint32_t*)cwo, (uint32_t*)cw1, (uint32_t*)cw2);

    // out projection + residual(x) -> x2 (fp32)
    dim3 g1024(EE / 128, ROWS / 128);
    gemm_res<<<g1024, 256, GEMM_SMEM>>>(o, cwo, bout, x, x2, EE, EE);

    // LN2: x2 -> h2 (fp16)
    ln_kernel<<<ROWS, 256>>>(x2, ln2_w, ln2_b, h2);

    // FC1 + GELU -> mid (fp16)
    dim3 g4096(FF / 128, ROWS / 128);
    gemm_gelu<<<g4096, 256, GEMM_SMEM>>>(h2, cw1, fc1_b, mid, FF, EE);

    // FC2 + residual(x2) -> out (fp32)
    gemm_res<<<g1024, 256, GEMM_SMEM>>>(mid, cw2, fc2_b, x2, out, EE, FF);
}

// round 17
// speedup vs baseline: 1.0402x; 1.0024x over previous
#include <cuda_runtime.h>
#include <cuda_fp16.h>
#include <math.h>
#include <stdint.h>

// Problem constants
#define LL 2048
#define NB 2
#define EE 1024
#define HH 16
#define DD 64
#define FF 4096
#define ROWS (LL*NB)   // 4096

// ---------------- scratch (no allocation allowed) ----------------
__device__ __half g_h  [ROWS*EE];
__device__ __half g_q  [ROWS*EE];
__device__ __half g_k  [ROWS*EE];
__device__ __half g_v  [ROWS*EE];
__device__ __half g_o  [ROWS*EE];
__device__ __half g_h2 [ROWS*EE];
__device__ __half g_mid[(size_t)ROWS*FF];
__device__ float  g_x2 [ROWS*EE];
// fp16 weight copies
__device__ __half g_wq [EE*EE];
__device__ __half g_wk [EE*EE];
__device__ __half g_wv [EE*EE];
__device__ __half g_wo [EE*EE];
__device__ __half g_w1 [FF*EE];
__device__ __half g_w2 [EE*FF];

// ---------------- helpers ----------------
__device__ __forceinline__ uint32_t h2pack(float a, float b) {
    __half2 h = __floats2half2_rn(a, b);
    return *reinterpret_cast<uint32_t*>(&h);
}
__device__ __forceinline__ float fexp2(float x) {
    float y;
    asm("ex2.approx.ftz.f32 %0, %1;" : "=f"(y) : "f"(x));
    return y;
}
__device__ __forceinline__ void mma_f16(float* c, const uint32_t* a, const uint32_t* b) {
    asm volatile(
        "mma.sync.aligned.m16n8k16.row.col.f32.f16.f16.f32 "
        "{%0,%1,%2,%3}, {%4,%5,%6,%7}, {%8,%9}, {%0,%1,%2,%3};\n"
        : "+f"(c[0]), "+f"(c[1]), "+f"(c[2]), "+f"(c[3])
        : "r"(a[0]), "r"(a[1]), "r"(a[2]), "r"(a[3]), "r"(b[0]), "r"(b[1]));
}
__device__ __forceinline__ void ldsm4(uint32_t& r0, uint32_t& r1, uint32_t& r2, uint32_t& r3,
                                      uint32_t addr) {
    asm volatile("ldmatrix.sync.aligned.m8n8.x4.shared.b16 {%0,%1,%2,%3}, [%4];\n"
                 : "=r"(r0), "=r"(r1), "=r"(r2), "=r"(r3) : "r"(addr));
}
__device__ __forceinline__ void ldsm4t(uint32_t& r0, uint32_t& r1, uint32_t& r2, uint32_t& r3,
                                       uint32_t addr) {
    asm volatile("ldmatrix.sync.aligned.m8n8.x4.trans.shared.b16 {%0,%1,%2,%3}, [%4];\n"
                 : "=r"(r0), "=r"(r1), "=r"(r2), "=r"(r3) : "r"(addr));
}
__device__ __forceinline__ void cp16(uint32_t saddr, const void* g) {
    asm volatile("cp.async.cg.shared.global [%0], [%1], 16;\n" :: "r"(saddr), "l"(g));
}
#define CP_COMMIT asm volatile("cp.async.commit_group;\n")
#define CP_WAIT1  asm volatile("cp.async.wait_group 1;\n")

__device__ __forceinline__ float gelu_exact(float t) {
    return 0.5f * t * (1.0f + erff(t * 0.70710678118654752f));
}

// ---------------- fused LN1 + QKV-weight f2h (both depend only on inputs) ----------------
// Blocks [0, ROWS): LayerNorm of one row. Blocks [ROWS, ROWS+QKV_CONV_BLOCKS):
// grid-stride fp32->fp16 conversion of wq/wk/wv (launched after the LN blocks,
// overlapping with them; all complete before the QKV GEMM launch).
#define QKV_CONV_BLOCKS 1536
#define QKV_CONV_TOTAL  786432   // 3 x 262144 float4 chunks

__global__ __launch_bounds__(256)
void ln1_f2h(const float* __restrict__ x, const float* __restrict__ w,
             const float* __restrict__ b, __half* __restrict__ out,
             const float4* __restrict__ wq, const float4* __restrict__ wk,
             const float4* __restrict__ wv,
             uint32_t* __restrict__ dq, uint32_t* __restrict__ dk,
             uint32_t* __restrict__ dv)
{
    const int tid = threadIdx.x;
    const int bid = blockIdx.x;

    if (bid >= ROWS) {
        // ---- QKV weight conversion ----
        int cid = bid - ROWS;
        for (int i = cid * 256 + tid; i < QKV_CONV_TOTAL; i += QKV_CONV_BLOCKS * 256) {
            const float4* s; uint32_t* d; int local;
            if (i < 262144)      { s = wq; d = dq; local = i; }
            else if (i < 524288) { s = wk; d = dk; local = i - 262144; }
            else                 { s = wv; d = dv; local = i - 524288; }
            float4 v = s[local];
            *(uint2*)&d[2*local] = make_uint2(h2pack(v.x, v.y), h2pack(v.z, v.w));
        }
        return;
    }

    // ---- LayerNorm row ----
    int row = bid;
    const float4* xr = (const float4*)(x + (size_t)row * EE);
    float4 v = xr[tid];
    float s  = v.x + v.y + v.z + v.w;
    float ss = v.x*v.x + v.y*v.y + v.z*v.z + v.w*v.w;
    #pragma unroll
    for (int o = 16; o > 0; o >>= 1) {
        s  += __shfl_xor_sync(0xffffffffu, s,  o);
        ss += __shfl_xor_sync(0xffffffffu, ss, o);
    }
    __shared__ float sbuf[8], ssbuf[8];
    if ((tid & 31) == 0) { sbuf[tid >> 5] = s; ssbuf[tid >> 5] = ss; }
    __syncthreads();
    float ts = 0.f, tss = 0.f;
    #pragma unroll
    for (int i = 0; i < 8; i++) { ts += sbuf[i]; tss += ssbuf[i]; }
    float mean = ts * (1.0f / EE);
    float var  = tss * (1.0f / EE) - mean * mean;
    float inv  = rsqrtf(var + 1e-5f);
    float4 w4 = ((const float4*)w)[tid];
    float4 b4 = ((const float4*)b)[tid];
    uint32_t* orow = (uint32_t*)(out + (size_t)row * EE);
    orow[2*tid]   = h2pack((v.x - mean)*inv*w4.x + b4.x, (v.y - mean)*inv*w4.y + b4.y);
    orow[2*tid+1] = h2pack((v.z - mean)*inv*w4.z + b4.z, (v.w - mean)*inv*w4.w + b4.w);
}

// ---------------- LayerNorm (standalone, for LN2) ----------------
__global__ __launch_bounds__(256)
void ln_kernel(const float* __restrict__ x, const float* __restrict__ w,
               const float* __restrict__ b, __half* __restrict__ out)
{
    int row = blockIdx.x;
    int tid = threadIdx.x;
    const float4* xr = (const float4*)(x + (size_t)row * EE);
    float4 v = xr[tid];
    float s  = v.x + v.y + v.z + v.w;
    float ss = v.x*v.x + v.y*v.y + v.z*v.z + v.w*v.w;
    #pragma unroll
    for (int o = 16; o > 0; o >>= 1) {
        s  += __shfl_xor_sync(0xffffffffu, s,  o);
        ss += __shfl_xor_sync(0xffffffffu, ss, o);
    }
    __shared__ float sbuf[8], ssbuf[8];
    if ((tid & 31) == 0) { sbuf[tid >> 5] = s; ssbuf[tid >> 5] = ss; }
    __syncthreads();
    float ts = 0.f, tss = 0.f;
    #pragma unroll
    for (int i = 0; i < 8; i++) { ts += sbuf[i]; tss += ssbuf[i]; }
    float mean = ts * (1.0f / EE);
    float var  = tss * (1.0f / EE) - mean * mean;
    float inv  = rsqrtf(var + 1e-5f);
    float4 w4 = ((const float4*)w)[tid];
    float4 b4 = ((const float4*)b)[tid];
    uint32_t* orow = (uint32_t*)(out + (size_t)row * EE);
    orow[2*tid]   = h2pack((v.x - mean)*inv*w4.x + b4.x, (v.y - mean)*inv*w4.y + b4.y);
    orow[2*tid+1] = h2pack((v.z - mean)*inv*w4.z + b4.z, (v.w - mean)*inv*w4.w + b4.w);
}

// ---------------- fp16 GEMM core (R6 config): BM=BN=128, BK=64, 8 warps 2x4 ----------------
#define KST 72                       // halves per smem row (144 B)
#define AST_BYTES (128*KST*2)        // 18432
#define STAGE_BYTES (2*AST_BYTES)    // 36864 (A+B)
#define NSTAGE 3
#define GEMM_SMEM (NSTAGE*STAGE_BYTES)   // 110592

__device__ __forceinline__ void issue_tile(uint32_t smu, const __half* A, const __half* B,
                                           int bm, int bn, int K, int k0, int slot)
{
    const int tid = threadIdx.x;
    uint32_t ao = smu + (unsigned)slot * STAGE_BYTES;
    uint32_t bo = ao + AST_BYTES;
    // 128 rows x 64 halves = 1024 chunks of 8 halves (16B) per operand
    #pragma unroll
    for (int c = 0; c < 4; c++) {
        int cid = tid + c * 256;
        int row = cid >> 3;
        int kc  = (cid & 7) * 8;
        cp16(ao + (unsigned)(row*KST + kc)*2, A + (size_t)(bm+row)*K + k0 + kc);
        cp16(bo + (unsigned)(row*KST + kc)*2, B + (size_t)(bn+row)*K + k0 + kc);
    }
}

__device__ __forceinline__ void gemm_main(const __half* __restrict__ A,
                                          const __half* __restrict__ B,
                                          int bm, int bn, int K, uint32_t smu,
                                          float c[4][4][4])
{
    const int tid  = threadIdx.x;
    const int warp = tid >> 5;
    const int lane = tid & 31;
    const int wm = (warp >> 2) * 64;
    const int wn = (warp & 3) * 32;
    const int ar = lane & 15;
    const int ac = (lane >> 4) * 8;
    const int br = (lane & 7) + ((lane >> 4) << 3);
    const int bc = ((lane >> 3) & 1) * 8;

    #pragma unroll
    for (int mt = 0; mt < 4; mt++)
        #pragma unroll
        for (int nt = 0; nt < 4; nt++)
            #pragma unroll
            for (int r = 0; r < 4; r++) c[mt][nt][r] = 0.f;

    const int NT = K >> 6;   // BK = 64
    issue_tile(smu, A, B, bm, bn, K, 0,  0); CP_COMMIT;
    issue_tile(smu, A, B, bm, bn, K, 64, 1); CP_COMMIT;

    for (int kt = 0; kt < NT; kt++) {
        CP_WAIT1;
        __syncthreads();
        if (kt + 2 < NT) issue_tile(smu, A, B, bm, bn, K, (kt+2) << 6, (kt+2) % NSTAGE);
        CP_COMMIT;

        const uint32_t sa = smu + (unsigned)(kt % NSTAGE) * STAGE_BYTES;
        const uint32_t sb = sa + AST_BYTES;

        #pragma unroll
        for (int kc = 0; kc < 4; kc++) {
            uint32_t a[4][4];
            #pragma unroll
            for (int mt = 0; mt < 4; mt++)
                ldsm4(a[mt][0], a[mt][1], a[mt][2], a[mt][3],
                      sa + (unsigned)((wm + mt*16 + ar)*KST + kc*16 + ac) * 2);
            uint32_t bf[4][2];
            #pragma unroll
            for (int p = 0; p < 2; p++) {
                uint32_t r0, r1, r2, r3;
                ldsm4(r0, r1, r2, r3,
                      sb + (unsigned)((wn + p*16 + br)*KST + kc*16 + bc) * 2);
                bf[2*p][0]   = r0; bf[2*p][1]   = r1;
                bf[2*p+1][0] = r2; bf[2*p+1][1] = r3;
            }
            #pragma unroll
            for (int mt = 0; mt < 4; mt++)
                #pragma unroll
                for (int nt = 0; nt < 4; nt++)
                    mma_f16(c[mt][nt], a[mt], bf[nt]);
        }
    }
}

// ---------------- GEMM with fp32 output + residual ----------------
__global__ __launch_bounds__(256, 2)
void gemm_res(const __half* __restrict__ A, const __half* __restrict__ B,
              const float* __restrict__ bias, const float* __restrict__ res,
              float* __restrict__ C, int Nn, int K)
{
    extern __shared__ uint32_t smg[];
    uint32_t smu = (uint32_t)__cvta_generic_to_shared(smg);
    const int bm = blockIdx.y * 128;
    const int bn = blockIdx.x * 128;
    float c[4][4][4];
    gemm_main(A, B, bm, bn, K, smu, c);

    const int tid = threadIdx.x, warp = tid >> 5, lane = tid & 31;
    const int g = lane >> 2, t = lane & 3;
    const int wm = (warp >> 2) * 64, wn = (warp & 3) * 32;
    #pragma unroll
    for (int mt = 0; mt < 4; mt++) {
        #pragma unroll
        for (int nt = 0; nt < 4; nt++) {
            int col = bn + wn + nt * 8 + t * 2;
            float2 bi = *(const float2*)(bias + col);
            #pragma unroll
            for (int h = 0; h < 2; h++) {
                int row = bm + wm + mt * 16 + g + h * 8;
                float2 r = *(const float2*)(res + (size_t)row * Nn + col);
                *(float2*)(C + (size_t)row * Nn + col) =
                    make_float2(c[mt][nt][h*2+0] + bi.x + r.x,
                                c[mt][nt][h*2+1] + bi.y + r.y);
            }
        }
    }
}

// ---------------- GEMM with GELU + fp16 output ----------------
__global__ __launch_bounds__(256, 2)
void gemm_gelu(const __half* __restrict__ A, const __half* __restrict__ B,
               const float* __restrict__ bias, __half* __restrict__ C, int Nn, int K)
{
    extern __shared__ uint32_t smg[];
    uint32_t smu = (uint32_t)__cvta_generic_to_shared(smg);
    const int bm = blockIdx.y * 128;
    const int bn = blockIdx.x * 128;
    float c[4][4][4];
    gemm_main(A, B, bm, bn, K, smu, c);

    const int tid = threadIdx.x, warp = tid >> 5, lane = tid & 31;
    const int g = lane >> 2, t = lane & 3;
    const int wm = (warp >> 2) * 64, wn = (warp & 3) * 32;
    #pragma unroll
    for (int mt = 0; mt < 4; mt++) {
        #pragma unroll
        for (int nt = 0; nt < 4; nt++) {
            int col = bn + wn + nt * 8 + t * 2;
            float2 bi = *(const float2*)(bias + col);
            #pragma unroll
            for (int h = 0; h < 2; h++) {
                int row = bm + wm + mt * 16 + g + h * 8;
                *(uint32_t*)(C + (size_t)row * Nn + col) =
                    h2pack(gelu_exact(c[mt][nt][h*2+0] + bi.x),
                           gelu_exact(c[mt][nt][h*2+1] + bi.y));
            }
        }
    }
}

// ---------------- fused QKV projection (fp16 out, scale on Q) ----------------
__global__ __launch_bounds__(256, 2)
void gemm_qkv(const __half* __restrict__ A,
              const __half* __restrict__ Bq, const __half* __restrict__ Bk, const __half* __restrict__ Bv,
              const float* __restrict__ bq, const float* __restrict__ bk, const float* __restrict__ bv,
              __half* __restrict__ Cq, __half* __restrict__ Ck, __half* __restrict__ Cv, int K)
{
    extern __shared__ uint32_t smg[];
    uint32_t smu = (uint32_t)__cvta_generic_to_shared(smg);
    const int bm  = blockIdx.y * 128;
    const int bng = blockIdx.x * 128;
    const int seg = bng >> 10;
    const int bn  = bng & 1023;
    const __half* B   = (seg == 0) ? Bq : (seg == 1) ? Bk : Bv;
    const float* bias = (seg == 0) ? bq : (seg == 1) ? bk : bv;
    __half*      C    = (seg == 0) ? Cq : (seg == 1) ? Ck : Cv;
    // Q scale = D^-0.5 * log2(e) so attention can use raw ex2 (base-2 softmax)
    const float scale = (seg == 0) ? 0.18033688011112042f : 1.0f;

    float c[4][4][4];
    gemm_main(A, B, bm, bn, K, smu, c);

    const int tid = threadIdx.x, warp = tid >> 5, lane = tid & 31;
    const int g = lane >> 2, t = lane & 3;
    const int wm = (warp >> 2) * 64, wn = (warp & 3) * 32;
    #pragma unroll
    for (int mt = 0; mt < 4; mt++) {
        #pragma unroll
        for (int nt = 0; nt < 4; nt++) {
            int col = bn + wn + nt * 8 + t * 2;
            float2 bi = *(const float2*)(bias + col);
            #pragma unroll
            for (int h = 0; h < 2; h++) {
                int row = bm + wm + mt * 16 + g + h * 8;
                *(uint32_t*)(C + (size_t)row * 1024 + col) =
                    h2pack((c[mt][nt][h*2+0] + bi.x) * scale,
                           (c[mt][nt][h*2+1] + bi.y) * scale);
            }
        }
    }
}

// ---------------- flash attention + TAIL-placed wo/fc1/fc2 f2h conversion ----------------
#define QB_TILES (LL/64)                 // 32
#define ATT_BLOCKS (QB_TILES * NB * HH)  // 1024
#define CONV_BLOCKS 512
#define CONV_TOTAL 2359296   // wo 262144 + w1 1048576 + w2 1048576 (float4)
#define ATST 72   // halves per smem row (144 B)
#define ATT_Q_HALVES (64*ATST)
#define ATT_KV_HALVES (64*ATST)
#define ATT_SMEM ((ATT_Q_HALVES + 4*ATT_KV_HALVES)*2)   // 46080 B

__device__ __forceinline__ void attn_issue_kv(uint32_t smu, const __half* k, const __half* v,
                                              int jb, int n, int hh, int slot)
{
    const int tid = threadIdx.x;   // 0..127
    uint32_t kbase = smu + (unsigned)(ATT_Q_HALVES + slot*2*ATT_KV_HALVES) * 2;
    #pragma unroll
    for (int c = 0; c < 8; c++) {
        int cid = tid + c * 128;
        int sel = cid >> 9;                   // 0=K, 1=V
        int id  = cid & 511;
        int row = id >> 3, c8 = (id & 7) * 8;
        const __half* src = sel ? v : k;
        uint32_t dst = kbase + (unsigned)(sel*ATT_KV_HALVES + row*ATST + c8) * 2;
        cp16(dst, src + ((size_t)((jb*64+row)*NB + n)*EE + hh*DD + c8));
    }
}

__global__ __launch_bounds__(128, 4)
void attn_h(const __half* __restrict__ q, const __half* __restrict__ k,
            const __half* __restrict__ v, __half* __restrict__ o,
            const float4* __restrict__ wo4, const float4* __restrict__ w14,
            const float4* __restrict__ w24,
            uint32_t* __restrict__ dwo, uint32_t* __restrict__ dw1,
            uint32_t* __restrict__ dw2)
{
    const int tid = threadIdx.x;
    const int bid = blockIdx.x;

    if (bid >= ATT_BLOCKS) {
        // ---- weight-conversion block (tail of launch order) ----
        int cid = bid - ATT_BLOCKS;                    // 0..511
        for (int i = cid * 128 + tid; i < CONV_TOTAL; i += CONV_BLOCKS * 128) {
            const float4* s; uint32_t* d; int local;
            if (i < 262144)       { s = wo4; d = dwo; local = i; }
            else if (i < 1310720) { s = w14; d = dw1; local = i - 262144; }
            else                  { s = w24; d = dw2; local = i - 1310720; }
            float4 vv = s[local];
            *(uint2*)&d[2*local] = make_uint2(h2pack(vv.x, vv.y), h2pack(vv.z, vv.w));
        }
        return;
    }

    extern __shared__ __half smh[];
    const uint32_t smu = (uint32_t)__cvta_generic_to_shared(smh);
    const uint32_t qsu = smu;

    const int qb = QB_TILES - 1 - (bid & (QB_TILES - 1));   // heavy-first
    const int nh = bid >> 5;
    const int n  = nh / HH;
    const int hh = nh % HH;
    const int warp = tid >> 5;
    const int lane = tid & 31;
    const int g = lane >> 2, t = lane & 3;
    const int m0 = warp * 16;
    const int ar = lane & 15, ac = (lane >> 4) * 8;
    const int br = (lane & 7) + ((lane >> 4) << 3), bc = ((lane >> 3) & 1) * 8;
    const int vr = (lane & 7) + (((lane >> 3) & 1) << 3);
    const int vc = (lane >> 4) * 8;

    // Q tile: 64 rows x 64 halves (pre-scaled by D^-0.5 * log2e)
    #pragma unroll
    for (int p = 0; p < 4; p++) {
        int idx = tid + p * 128;
        int row = idx >> 3, c8 = (idx & 7) * 8;
        *(uint4*)&smh[row*ATST + c8] =
            *(const uint4*)(q + ((size_t)((qb*64+row)*NB + n)*EE + hh*DD + c8));
    }

    attn_issue_kv(smu, k, v, 0, n, hh, 0); CP_COMMIT;

    float l_i[2] = {0.f, 0.f};
    float accO[8][4];
    #pragma unroll
    for (int dt = 0; dt < 8; dt++)
        #pragma unroll
        for (int r = 0; r < 4; r++) accO[dt][r] = 0.f;

    for (int jb = 0; jb <= qb; jb++) {
        if (jb + 1 <= qb) attn_issue_kv(smu, k, v, jb+1, n, hh, (jb+1) & 1);
        CP_COMMIT;
        CP_WAIT1;
        __syncthreads();

        const uint32_t ksu = smu + (unsigned)(ATT_Q_HALVES + (jb & 1)*2*ATT_KV_HALVES) * 2;
        const uint32_t vsu = ksu + (unsigned)ATT_KV_HALVES * 2;

        // S' = (log2e/sqrt(D)) * Q K^T (16 x 64 per warp)
        float sc[8][4];
        #pragma unroll
        for (int nt = 0; nt < 8; nt++)
            #pragma unroll
            for (int r = 0; r < 4; r++) sc[nt][r] = 0.f;

        #pragma unroll
        for (int kc = 0; kc < 4; kc++) {
            uint32_t a[4];
            ldsm4(a[0], a[1], a[2], a[3],
                  qsu + (unsigned)((m0 + ar)*ATST + kc*16 + ac) * 2);
            #pragma unroll
            for (int p = 0; p < 4; p++) {
                uint32_t r0, r1, r2, r3;
                ldsm4(r0, r1, r2, r3,
                      ksu + (unsigned)((p*16 + br)*ATST + kc*16 + bc) * 2);
                uint32_t b0[2] = {r0, r1}, b1[2] = {r2, r3};
                mma_f16(sc[2*p],   a, b0);
                mma_f16(sc[2*p+1], a, b1);
            }
        }

        // causal mask on diagonal tile
        if (jb == qb) {
            int r0 = m0 + g, r1 = m0 + g + 8;
            #pragma unroll
            for (int nt = 0; nt < 8; nt++) {
                int col = nt * 8 + t * 2;
                if (col     > r0) sc[nt][0] = -1e30f;
                if (col + 1 > r0) sc[nt][1] = -1e30f;
                if (col     > r1) sc[nt][2] = -1e30f;
                if (col + 1 > r1) sc[nt][3] = -1e30f;
            }
        }

        // fixed-reference softmax: p = 2^{S'}; accumulate row sums (quad-reduced)
        float sum0 = 0.f, sum1 = 0.f;
        #pragma unroll
        for (int nt = 0; nt < 8; nt++) {
            sc[nt][0] = fexp2(sc[nt][0]); sum0 += sc[nt][0];
            sc[nt][1] = fexp2(sc[nt][1]); sum0 += sc[nt][1];
            sc[nt][2] = fexp2(sc[nt][2]); sum1 += sc[nt][2];
            sc[nt][3] = fexp2(sc[nt][3]); sum1 += sc[nt][3];
        }
        #pragma unroll
        for (int off = 1; off < 4; off <<= 1) {
            sum0 += __shfl_xor_sync(0xffffffffu, sum0, off);
            sum1 += __shfl_xor_sync(0xffffffffu, sum1, off);
        }
        l_i[0] += sum0;
        l_i[1] += sum1;

        // O += P V (S C-frag == P A-frag; V B-frags via ldsm.trans)
        #pragma unroll
        for (int kc = 0; kc < 4; kc++) {
            uint32_t a[4];
            a[0] = h2pack(sc[2*kc][0],   sc[2*kc][1]);
            a[1] = h2pack(sc[2*kc][2],   sc[2*kc][3]);
            a[2] = h2pack(sc[2*kc+1][0], sc[2*kc+1][1]);
            a[3] = h2pack(sc[2*kc+1][2], sc[2*kc+1][3]);
            #pragma unroll
            for (int dp = 0; dp < 4; dp++) {
                uint32_t r0, r1, r2, r3;
                ldsm4t(r0, r1, r2, r3,
                       vsu + (unsigned)((kc*16 + vr)*ATST + dp*16 + vc) * 2);
                uint32_t b0[2] = {r0, r1}, b1[2] = {r2, r3};
                mma_f16(accO[2*dp],   a, b0);
                mma_f16(accO[2*dp+1], a, b1);
            }
        }
        __syncthreads();
    }

    // normalize + store fp16
    float inv0 = 1.0f / l_i[0], inv1 = 1.0f / l_i[1];
    int l0 = qb*64 + m0 + g;
    int l1 = l0 + 8;
    #pragma unroll
    for (int dt = 0; dt < 8; dt++) {
        int d = hh*DD + dt*8 + t*2;
        *(uint32_t*)(o + ((size_t)(l0*NB + n)*EE + d)) =
            h2pack(accO[dt][0]*inv0, accO[dt][1]*inv0);
        *(uint32_t*)(o + ((size_t)(l1*NB + n)*EE + d)) =
            h2pack(accO[dt][2]*inv1, accO[dt][3]*inv1);
    }
}

// ---------------- launch ----------------
extern "C" void kernel_launch(void* const* d_in, const int* in_sizes, int n_in,
                              void* d_out, int out_size)
{
    const float* x     = (const float*)d_in[0];
    const float* ln1_w = (const float*)d_in[1];
    const float* ln1_b = (const float*)d_in[2];
    const float* wq    = (const float*)d_in[3];
    const float* bq    = (const float*)d_in[4];
    const float* wk    = (const float*)d_in[5];
    const float* bk    = (const float*)d_in[6];
    const float* wv    = (const float*)d_in[7];
    const float* bv    = (const float*)d_in[8];
    const float* wout  = (const float*)d_in[9];
    const float* bout  = (const float*)d_in[10];
    const float* ln2_w = (const float*)d_in[11];
    const float* ln2_b = (const float*)d_in[12];
    const float* fc1_w = (const float*)d_in[13];
    const float* fc1_b = (const float*)d_in[14];
    const float* fc2_w = (const float*)d_in[15];
    const float* fc2_b = (const float*)d_in[16];
    float* out = (float*)d_out;

    __half *h, *q, *k, *v, *o, *h2, *mid;
    __half *cwq, *cwk, *cwv, *cwo, *cw1, *cw2;
    float  *x2;
    cudaGetSymbolAddress((void**)&h,   g_h);
    cudaGetSymbolAddress((void**)&q,   g_q);
    cudaGetSymbolAddress((void**)&k,   g_k);
    cudaGetSymbolAddress((void**)&v,   g_v);
    cudaGetSymbolAddress((void**)&o,   g_o);
    cudaGetSymbolAddress((void**)&h2,  g_h2);
    cudaGetSymbolAddress((void**)&mid, g_mid);
    cudaGetSymbolAddress((void**)&x2,  g_x2);
    cudaGetSymbolAddress((void**)&cwq, g_wq);
    cudaGetSymbolAddress((void**)&cwk, g_wk);
    cudaGetSymbolAddress((void**)&cwv, g_wv);
    cudaGetSymbolAddress((void**)&cwo, g_wo);
    cudaGetSymbolAddress((void**)&cw1, g_w1);
    cudaGetSymbolAddress((void**)&cw2, g_w2);

    cudaFuncSetAttribute(gemm_qkv,  cudaFuncAttributeMaxDynamicSharedMemorySize, GEMM_SMEM);
    cudaFuncSetAttribute(gemm_res,  cudaFuncAttributeMaxDynamicSharedMemorySize, GEMM_SMEM);
    cudaFuncSetAttribute(gemm_gelu, cudaFuncAttributeMaxDynamicSharedMemorySize, GEMM_SMEM);
    cudaFuncSetAttribute(attn_h,    cudaFuncAttributeMaxDynamicSharedMemorySize, ATT_SMEM);

    // fused LN1 + QKV weight conversion (both depend only on inputs)
    ln1_f2h<<<ROWS + QKV_CONV_BLOCKS, 256>>>(
        x, ln1_w, ln1_b, h,
        (const float4*)wq, (const float4*)wk, (const float4*)wv,
        (uint32_t*)cwq, (uint32_t*)cwk, (uint32_t*)cwv);

    // fused QKV (M=4096, N=3*1024, K=1024); D^-0.5*log2e folded into Q
    dim3 gqkv(3 * EE / 128, ROWS / 128);
    gemm_qkv<<<gqkv, 256, GEMM_SMEM>>>(h, cwq, cwk, cwv, bq, bk, bv, q, k, v, EE);

    // causal flash attention (R14 ordering) + tail-placed wo/fc1/fc2 conversion
    attn_h<<<ATT_BLOCKS + CONV_BLOCKS, 128, ATT_SMEM>>>(
        q, k, v, o,
        (const float4*)wout, (const float4*)fc1_w, (const float4*)fc2_w,
        (uint32_t*)cwo, (uint32_t*)cw1, (uint32_t*)cw2);

    // out projection + residual(x) -> x2 (fp32)
    dim3 g1024(EE / 128, ROWS / 128);
    gemm_res<<<g1024, 256, GEMM_SMEM>>>(o, cwo, bout, x, x2, EE, EE);

    // LN2: x2 -> h2 (fp16)
    ln_kernel<<<ROWS, 256>>>(x2, ln2_w, ln2_b, h2);

    // FC1 + GELU -> mid (fp16)
    dim3 g4096(FF / 128, ROWS / 128);
    gemm_gelu<<<g4096, 256, GEMM_SMEM>>>(h2, cw1, fc1_b, mid, FF, EE);

    // FC2 + residual(x2) -> out (fp32)
    gemm_res<<<g1024, 256, GEMM_SMEM>>>(mid, cw2, fc2_b, x2, out, EE, FF);
}